// round 13
// baseline (speedup 1.0000x reference)
#include <cuda_runtime.h>
#include <cuda_bf16.h>

// Output: [Cm1, 1, R, 85] fp32 flat (NC = 81). One-pass specialized kernel.
//
// Group structure: 4 rows = 340 elements = exactly 85 float4s.
// Boundary float4 positions (touch box slots): {20,21,41,42,62,63,84}.
// Fast remap: w in [0,78) -> plane pos p = w + 2*cnt, cnt=(w>=20)+(w>=39)+(w>=58);
//             cls float4 idx = 81g + w + cnt.
//
// Block = 8 warps. Lane = float4 position, warp = class offset within an
// 8-class group (blockIdx.y). All 8 warps read the SAME 512B cls region ->
// 1 L2 access + 7 L1 hits, while keeping R10's 1-LDG/1-STG per thread and
// per-warp contiguous 512B stores.

#define CGRP 8

__global__ void __launch_bounds__(256)
bb_l1share_kernel(const float* __restrict__ cls,     // [R, 81]
                  const float4* __restrict__ cls4,
                  const float4* __restrict__ regr4,  // [R, Cm1] of float4
                  const float4* __restrict__ rois,   // [R] of float4
                  float4* __restrict__ out4,
                  int perC4,        // 85*R/4
                  int R, int Cm1,
                  int fastBlocks,   // fastCount/32 blocks
                  int fastCount,    // 78*(R/4), multiple of 32
                  int slowCount,    // 7*(R/4)
                  float invW, float invH)
{
    const int lane = threadIdx.x & 31;
    const int wrp  = threadIdx.x >> 5;            // class offset in group
    const int c    = blockIdx.y * CGRP + wrp;
    const bool cOK = (c < Cm1);

    if (blockIdx.x < (unsigned)fastBlocks) {
        // ---------- FAST: pure cls copy, 1 LDG (L1-shared) + 1 STG ----------
        int tf = blockIdx.x * 32 + lane;          // position index, < fastCount
        unsigned w = (unsigned)tf % 78u;
        unsigned g = (unsigned)tf / 78u;
        unsigned cnt = (w >= 20u) + (w >= 39u) + (w >= 58u);
        int t   = (int)(85u * g + w + 2u * cnt);  // float4 index in plane
        int idx = (int)(81u * g + w + cnt);       // float4 index in cls

        float4 v = __ldg(&cls4[idx]);             // warp0 misses, rest L1-hit
        if (cOK)
            out4[(size_t)c * (size_t)perC4 + (size_t)t] = v;
        return;
    }

    // ---------- SLOW: boundary float4s (contain box elements) ----------
    int u = (blockIdx.x - fastBlocks) * 32 + lane;
    if (u >= slowCount || !cOK) return;
    unsigned q = (unsigned)u % 7u;
    unsigned g = (unsigned)u / 7u;
    unsigned p = (q == 6u) ? 84u : (20u + 21u * (q >> 1) + (q & 1u));
    int t = (int)(85u * g + p);

    unsigned rem0 = (unsigned)t << 2;
    unsigned r  = rem0 / 85u;
    unsigned k0 = rem0 - r * 85u;

    float4 roi = __ldg(&rois[r]);                      // x, y, w, h
    float4 tg  = __ldg(&regr4[(size_t)r * Cm1 + c]);   // tx, ty, tw, th

    float gx = rintf(fmaf(roi.z, tg.x, roi.x));
    float gy = rintf(fmaf(roi.w, tg.y, roi.y));
    float gw = rintf(roi.z * expf(tg.z));
    float gh = rintf(roi.w * expf(tg.w));

    float b[4];
    b[0] = gx * invW;
    b[1] = gy * invH;
    b[2] = (gx + gw) * invW;
    b[3] = (gy + gh) * invH;

    float v[4];
#pragma unroll
    for (int i = 0; i < 4; ++i) {
        int k = (int)k0 + i;
        int rr = (int)r;
        if (k >= 85) { k -= 85; ++rr; }   // wrap lands in cls of next row
        v[i] = (k < 81) ? __ldg(&cls[(size_t)rr * 81 + k]) : b[k - 81];
    }
    float4 o; o.x = v[0]; o.y = v[1]; o.z = v[2]; o.w = v[3];
    out4[(size_t)c * (size_t)perC4 + (size_t)t] = o;
}

// ---------------- R10 one-pass kernel (proven 180us) as 85-fallback ----------------
__global__ void __launch_bounds__(256)
bb_onepass_kernel(const float* __restrict__ cls, const float4* __restrict__ cls4,
                  const float4* __restrict__ regr4, const float4* __restrict__ rois,
                  float4* __restrict__ out4, int perC4, int R, int Cm1,
                  int fastBlocks, int fastCount, int slowCount,
                  float invW, float invH)
{
    const int c = blockIdx.y;
    float4* plane = out4 + (size_t)c * (size_t)perC4;

    if (blockIdx.x < (unsigned)fastBlocks) {
        int tf = blockIdx.x * 256 + threadIdx.x;
        if (tf >= fastCount) return;
        unsigned w = (unsigned)tf % 78u;
        unsigned g = (unsigned)tf / 78u;
        unsigned cnt = (w >= 20u) + (w >= 39u) + (w >= 58u);
        int t   = (int)(85u * g + w + 2u * cnt);
        int idx = (int)(81u * g + w + cnt);
        plane[t] = __ldg(&cls4[idx]);
        return;
    }
    int u = (blockIdx.x - fastBlocks) * 256 + threadIdx.x;
    if (u >= slowCount) return;
    unsigned q = (unsigned)u % 7u;
    unsigned g = (unsigned)u / 7u;
    unsigned p = (q == 6u) ? 84u : (20u + 21u * (q >> 1) + (q & 1u));
    int t = (int)(85u * g + p);
    unsigned rem0 = (unsigned)t << 2;
    unsigned r  = rem0 / 85u;
    unsigned k0 = rem0 - r * 85u;
    float4 roi = __ldg(&rois[r]);
    float4 tg  = __ldg(&regr4[(size_t)r * Cm1 + c]);
    float gx = rintf(fmaf(roi.z, tg.x, roi.x));
    float gy = rintf(fmaf(roi.w, tg.y, roi.y));
    float gw = rintf(roi.z * expf(tg.z));
    float gh = rintf(roi.w * expf(tg.w));
    float b[4];
    b[0] = gx * invW; b[1] = gy * invH;
    b[2] = (gx + gw) * invW; b[3] = (gy + gh) * invH;
    float v[4];
#pragma unroll
    for (int i = 0; i < 4; ++i) {
        int k = (int)k0 + i;
        int rr = (int)r;
        if (k >= 85) { k -= 85; ++rr; }
        v[i] = (k < 81) ? __ldg(&cls[(size_t)rr * 81 + k]) : b[k - 81];
    }
    float4 o; o.x = v[0]; o.y = v[1]; o.z = v[2]; o.w = v[3];
    plane[t] = o;
}

// ---------------- Generic scalar fallback ----------------
__global__ void __launch_bounds__(256)
bb_generic_kernel(const float* __restrict__ regr, const float* __restrict__ cls,
                  const float4* __restrict__ rois, float* __restrict__ out,
                  int R, int Cm1, int NC, float invW, float invH, long long total)
{
    long long idx = (long long)blockIdx.x * blockDim.x + threadIdx.x;
    long long stride = (long long)gridDim.x * blockDim.x;
    const int rowlen = NC + 4;
    const long long perC = (long long)R * rowlen;
    for (; idx < total; idx += stride) {
        int c   = (int)(idx / perC);
        int rem = (int)(idx - (long long)c * perC);
        int r   = rem / rowlen;
        int k   = rem - r * rowlen;
        float val;
        if (k < NC) {
            val = cls[(long long)r * NC + k];
        } else {
            float4 roi = __ldg(&rois[r]);
            const float* rg = regr + ((long long)r * Cm1 + c) * 4;
            int comp = k - NC;
            if (comp == 0)      val = rintf(fmaf(roi.z, rg[0], roi.x)) * invW;
            else if (comp == 1) val = rintf(fmaf(roi.w, rg[1], roi.y)) * invH;
            else if (comp == 2) val = (rintf(fmaf(roi.z, rg[0], roi.x)) +
                                       rintf(roi.z * expf(rg[2]))) * invW;
            else                val = (rintf(fmaf(roi.w, rg[1], roi.y)) +
                                       rintf(roi.w * expf(rg[3]))) * invH;
        }
        out[idx] = val;
    }
}

extern "C" void kernel_launch(void* const* d_in, const int* in_sizes, int n_in,
                              void* d_out, int out_size)
{
    const float*  regr = (const float*)d_in[0];   // [1, R, 4*Cm1]
    const float*  cls  = (const float*)d_in[1];   // [1, R, NC]
    const float4* rois = (const float4*)d_in[2];  // [1, R, 4]

    const int R   = in_sizes[2] / 4;
    const int Cm1 = in_sizes[0] / (R * 4);
    const int NC  = in_sizes[1] / R;
    const int rowlen = NC + 4;

    long long hw = (long long)in_sizes[3] / 3;    // H = W = isqrt(b_elems/3)
    int side = 1;
    while ((long long)(side + 1) * (side + 1) <= hw) ++side;
    const float invW = 1.0f / (float)side;
    const float invH = 1.0f / (float)side;

    float* out = (float*)d_out;
    const long long perC  = (long long)R * rowlen;
    const long long total = (long long)out_size;

    if (rowlen == 85 && (R % 4) == 0 &&
        total == (long long)Cm1 * perC && (perC % 4) == 0) {
        const int perC4     = (int)(perC >> 2);
        const int groups    = R / 4;
        const int fastCount = 78 * groups;
        const int slowCount = 7 * groups;

        if ((fastCount % 32) == 0) {
            // L1-sharing layout: lane = position, warp = class-in-group
            const int fastBlocks = fastCount / 32;
            const int slowBlocks = (slowCount + 31) / 32;
            dim3 grid(fastBlocks + slowBlocks, (Cm1 + CGRP - 1) / CGRP);
            bb_l1share_kernel<<<grid, 256>>>(
                cls, (const float4*)cls, (const float4*)regr, rois,
                (float4*)out, perC4, R, Cm1,
                fastBlocks, fastCount, slowCount, invW, invH);
        } else {
            // Proven R10 layout
            const int fastBlocks = (fastCount + 255) / 256;
            const int slowBlocks = (slowCount + 255) / 256;
            dim3 grid(fastBlocks + slowBlocks, Cm1);
            bb_onepass_kernel<<<grid, 256>>>(
                cls, (const float4*)cls, (const float4*)regr, rois,
                (float4*)out, perC4, R, Cm1,
                fastBlocks, fastCount, slowCount, invW, invH);
        }
    } else {
        long long blocks = (total + 255) / 256;
        if (blocks > 262144) blocks = 262144;
        bb_generic_kernel<<<(unsigned)blocks, 256>>>(
            regr, cls, rois, out, R, Cm1, NC, invW, invH, total);
    }
}

// round 14
// speedup vs baseline: 1.6494x; 1.6494x over previous
#include <cuda_runtime.h>
#include <cuda_bf16.h>

// Output: [Cm1, 1, R, 85] fp32 flat (NC = 81). One-pass specialized kernel,
// derived from the proven R10 layout (180us) with two deltas:
//   * fast path: 2 float4 positions per thread (512-position blocks, ILP=2)
//   * __stcs streaming stores everywhere (output is never re-read)
//
// Group structure: 4 rows = 340 elements = exactly 85 float4s.
// Boundary float4 positions (touch box slots): {20,21,41,42,62,63,84}.
// Fast remap: w in [0,78) -> p = w + 2*cnt, cnt=(w>=20)+(w>=39)+(w>=58);
//             cls float4 idx = 81g + w + cnt.

__global__ void __launch_bounds__(256)
bb_onepass2_kernel(const float* __restrict__ cls,     // [R, 81]
                   const float4* __restrict__ cls4,
                   const float4* __restrict__ regr4,  // [R, Cm1] of float4
                   const float4* __restrict__ rois,   // [R] of float4
                   float4* __restrict__ out4,
                   int perC4,        // 85*R/4
                   int R, int Cm1,
                   int fastBlocks,   // ceil(fastCount/512)
                   int fastCount,    // 78*(R/4)
                   int slowCount,    // 7*(R/4)
                   float invW, float invH)
{
    const int c = blockIdx.y;
    float4* plane = out4 + (size_t)c * (size_t)perC4;

    if (blockIdx.x < (unsigned)fastBlocks) {
        // ---------- FAST: 2 consecutive-chunk copies per thread ----------
        int base = blockIdx.x * 512 + threadIdx.x;
#pragma unroll
        for (int s = 0; s < 2; ++s) {
            int tf = base + s * 256;
            if (tf < fastCount) {
                unsigned w = (unsigned)tf % 78u;         // const-div
                unsigned g = (unsigned)tf / 78u;
                unsigned cnt = (w >= 20u) + (w >= 39u) + (w >= 58u);
                int t   = (int)(85u * g + w + 2u * cnt); // plane float4 index
                int idx = (int)(81u * g + w + cnt);      // cls float4 index
                float4 v = __ldg(&cls4[idx]);
                __stcs(&plane[t], v);
            }
        }
        return;
    }

    // ---------- SLOW: boundary float4s (contain box elements) ----------
    int u = (blockIdx.x - fastBlocks) * 256 + threadIdx.x;
    if (u >= slowCount) return;
    unsigned q = (unsigned)u % 7u;
    unsigned g = (unsigned)u / 7u;
    unsigned p = (q == 6u) ? 84u : (20u + 21u * (q >> 1) + (q & 1u));
    int t = (int)(85u * g + p);

    unsigned rem0 = (unsigned)t << 2;
    unsigned r  = rem0 / 85u;
    unsigned k0 = rem0 - r * 85u;

    float4 roi = __ldg(&rois[r]);                      // x, y, w, h
    float4 tg  = __ldg(&regr4[(size_t)r * Cm1 + c]);   // tx, ty, tw, th

    float gx = rintf(fmaf(roi.z, tg.x, roi.x));
    float gy = rintf(fmaf(roi.w, tg.y, roi.y));
    float gw = rintf(roi.z * expf(tg.z));
    float gh = rintf(roi.w * expf(tg.w));

    float b[4];
    b[0] = gx * invW;
    b[1] = gy * invH;
    b[2] = (gx + gw) * invW;
    b[3] = (gy + gh) * invH;

    float v[4];
#pragma unroll
    for (int i = 0; i < 4; ++i) {
        int k = (int)k0 + i;
        int rr = (int)r;
        if (k >= 85) { k -= 85; ++rr; }   // wrap lands in cls of next row
        v[i] = (k < 81) ? __ldg(&cls[(size_t)rr * 81 + k]) : b[k - 81];
    }
    float4 o; o.x = v[0]; o.y = v[1]; o.z = v[2]; o.w = v[3];
    __stcs(&plane[t], o);
}

// ---------------- Generic scalar fallback ----------------
__global__ void __launch_bounds__(256)
bb_generic_kernel(const float* __restrict__ regr, const float* __restrict__ cls,
                  const float4* __restrict__ rois, float* __restrict__ out,
                  int R, int Cm1, int NC, float invW, float invH, long long total)
{
    long long idx = (long long)blockIdx.x * blockDim.x + threadIdx.x;
    long long stride = (long long)gridDim.x * blockDim.x;
    const int rowlen = NC + 4;
    const long long perC = (long long)R * rowlen;
    for (; idx < total; idx += stride) {
        int c   = (int)(idx / perC);
        int rem = (int)(idx - (long long)c * perC);
        int r   = rem / rowlen;
        int k   = rem - r * rowlen;
        float val;
        if (k < NC) {
            val = cls[(long long)r * NC + k];
        } else {
            float4 roi = __ldg(&rois[r]);
            const float* rg = regr + ((long long)r * Cm1 + c) * 4;
            int comp = k - NC;
            if (comp == 0)      val = rintf(fmaf(roi.z, rg[0], roi.x)) * invW;
            else if (comp == 1) val = rintf(fmaf(roi.w, rg[1], roi.y)) * invH;
            else if (comp == 2) val = (rintf(fmaf(roi.z, rg[0], roi.x)) +
                                       rintf(roi.z * expf(rg[2]))) * invW;
            else                val = (rintf(fmaf(roi.w, rg[1], roi.y)) +
                                       rintf(roi.w * expf(rg[3]))) * invH;
        }
        out[idx] = val;
    }
}

extern "C" void kernel_launch(void* const* d_in, const int* in_sizes, int n_in,
                              void* d_out, int out_size)
{
    const float*  regr = (const float*)d_in[0];   // [1, R, 4*Cm1]
    const float*  cls  = (const float*)d_in[1];   // [1, R, NC]
    const float4* rois = (const float4*)d_in[2];  // [1, R, 4]

    const int R   = in_sizes[2] / 4;
    const int Cm1 = in_sizes[0] / (R * 4);
    const int NC  = in_sizes[1] / R;
    const int rowlen = NC + 4;

    long long hw = (long long)in_sizes[3] / 3;    // H = W = isqrt(b_elems/3)
    int side = 1;
    while ((long long)(side + 1) * (side + 1) <= hw) ++side;
    const float invW = 1.0f / (float)side;
    const float invH = 1.0f / (float)side;

    float* out = (float*)d_out;
    const long long perC  = (long long)R * rowlen;
    const long long total = (long long)out_size;

    if (rowlen == 85 && (R % 4) == 0 &&
        total == (long long)Cm1 * perC && (perC % 4) == 0) {
        const int perC4     = (int)(perC >> 2);
        const int groups    = R / 4;
        const int fastCount = 78 * groups;
        const int slowCount = 7 * groups;
        const int fastBlocks = (fastCount + 511) / 512;
        const int slowBlocks = (slowCount + 255) / 256;
        dim3 grid(fastBlocks + slowBlocks, Cm1);
        bb_onepass2_kernel<<<grid, 256>>>(
            cls, (const float4*)cls, (const float4*)regr, rois,
            (float4*)out, perC4, R, Cm1,
            fastBlocks, fastCount, slowCount, invW, invH);
    } else {
        long long blocks = (total + 255) / 256;
        if (blocks > 262144) blocks = 262144;
        bb_generic_kernel<<<(unsigned)blocks, 256>>>(
            regr, cls, rois, out, R, Cm1, NC, invW, invH, total);
    }
}